// round 1
// baseline (speedup 1.0000x reference)
#include <cuda_runtime.h>
#include <cstdint>

#define B_  64
#define T_  320
#define E_  1024
#define H_  16
#define HS_ 64
#define P_  4096
#define M_  (B_ * T_)          // 20480 tokens
#define EPS 1e-5f
#define SCALE 0.03125f          // E^-0.5 = 1/32

// ---------------- scratch (device globals; no allocation allowed) ----------------
__device__ float g_h[(size_t)M_ * E_];          // LN output (reused for ln1 & ln2)
__device__ float g_w3[(size_t)E_ * 3 * E_];     // packed QKV weights [K=1024][N=3072]
__device__ float g_qkv[(size_t)M_ * 3 * E_];    // q|k|v per token
__device__ float g_attn[(size_t)M_ * E_];       // attention out in [B,T,E]
__device__ float g_x2[(size_t)M_ * E_];         // after out-proj residual
__device__ float g_u[(size_t)M_ * P_];          // FFN hidden

// ---------------- pack Wq/Wk/Wv -> [k][which*1024 + h*64 + d] ----------------
__global__ void pack_w_kernel(const float* __restrict__ Wq,
                              const float* __restrict__ Wk,
                              const float* __restrict__ Wv,
                              float* __restrict__ W3) {
    int idx = blockIdx.x * 256 + threadIdx.x;   // over 3*E*E = 3145728
    int k = idx / 3072;
    int n = idx % 3072;
    int which = n >> 10;
    int rem = n & 1023;
    int hh = rem >> 6;
    int d = rem & 63;
    const float* W = (which == 0) ? Wq : (which == 1) ? Wk : Wv;
    W3[idx] = W[(size_t)hh * E_ * HS_ + (size_t)k * HS_ + d];
}

// ---------------- layernorm: one block per row ----------------
__device__ __forceinline__ float blockSum256(float v, float* sh) {
    __syncthreads();
    #pragma unroll
    for (int o = 16; o > 0; o >>= 1) v += __shfl_xor_sync(0xffffffffu, v, o);
    if ((threadIdx.x & 31) == 0) sh[threadIdx.x >> 5] = v;
    __syncthreads();
    if (threadIdx.x < 32) {
        float t = (threadIdx.x < 8) ? sh[threadIdx.x] : 0.0f;
        #pragma unroll
        for (int o = 4; o > 0; o >>= 1) t += __shfl_xor_sync(0xffffffffu, t, o);
        if (threadIdx.x == 0) sh[0] = t;
    }
    __syncthreads();
    return sh[0];
}

__global__ void ln_kernel(const float* __restrict__ x, const float* __restrict__ w,
                          const float* __restrict__ bb, float* __restrict__ out) {
    __shared__ float sh[8];
    size_t row = blockIdx.x;
    int tid = threadIdx.x;
    const float4 v = ((const float4*)(x + row * E_))[tid];
    float s = v.x + v.y + v.z + v.w;
    s = blockSum256(s, sh);
    float mu = s * (1.0f / E_);
    float dx = v.x - mu, dy = v.y - mu, dz = v.z - mu, dw = v.w - mu;
    float ss = dx * dx + dy * dy + dz * dz + dw * dw;
    ss = blockSum256(ss, sh);
    float inv = rsqrtf(ss * (1.0f / E_) + EPS);
    float4 w4 = ((const float4*)w)[tid];
    float4 b4 = ((const float4*)bb)[tid];
    float4 r;
    r.x = dx * inv * w4.x + b4.x;
    r.y = dy * inv * w4.y + b4.y;
    r.z = dz * inv * w4.z + b4.z;
    r.w = dw * inv * w4.w + b4.w;
    ((float4*)(out + row * E_))[tid] = r;
}

// ---------------- generic 128x128x8 SGEMM, 8x8 microtile, epilogue fused ----------------
template <bool BIAS, bool RESID, bool RELU>
__global__ __launch_bounds__(256, 2) void gemm128_kernel(
    const float* __restrict__ A, const float* __restrict__ Bm,
    const float* __restrict__ bias, const float* __restrict__ Rm,
    float* __restrict__ C, int Ndim, int K) {
    __shared__ float As[8][128];
    __shared__ float Bs[8][132];

    int tid = threadIdx.x;
    int bx = blockIdx.x, by = blockIdx.y;
    int tx = tid & 15, ty = tid >> 4;

    const float* Ap = A + (size_t)by * 128 * K;
    const float* Bp = Bm + (size_t)bx * 128;

    int a_row = tid >> 1, a_col = (tid & 1) * 4;
    int b_row = tid >> 5, b_col = (tid & 31) * 4;

    float4 aF = *(const float4*)(Ap + (size_t)a_row * K + a_col);
    float4 bF = *(const float4*)(Bp + (size_t)b_row * Ndim + b_col);

    float acc[8][8];
    #pragma unroll
    for (int i = 0; i < 8; i++)
        #pragma unroll
        for (int j = 0; j < 8; j++) acc[i][j] = 0.0f;

    int nk = K >> 3;
    int kt = 0;
    while (true) {
        As[a_col + 0][a_row] = aF.x;
        As[a_col + 1][a_row] = aF.y;
        As[a_col + 2][a_row] = aF.z;
        As[a_col + 3][a_row] = aF.w;
        *(float4*)&Bs[b_row][b_col] = bF;
        __syncthreads();
        ++kt;
        if (kt < nk) {
            aF = *(const float4*)(Ap + (size_t)a_row * K + kt * 8 + a_col);
            bF = *(const float4*)(Bp + (size_t)(kt * 8 + b_row) * Ndim + b_col);
        }
        #pragma unroll
        for (int kk = 0; kk < 8; kk++) {
            float ar[8], br2[8];
            *(float4*)&ar[0] = *(float4*)&As[kk][ty * 8];
            *(float4*)&ar[4] = *(float4*)&As[kk][ty * 8 + 4];
            *(float4*)&br2[0] = *(float4*)&Bs[kk][tx * 8];
            *(float4*)&br2[4] = *(float4*)&Bs[kk][tx * 8 + 4];
            #pragma unroll
            for (int i = 0; i < 8; i++)
                #pragma unroll
                for (int j = 0; j < 8; j++) acc[i][j] += ar[i] * br2[j];
        }
        if (kt >= nk) break;
        __syncthreads();
    }

    int m0 = by * 128 + ty * 8;
    int n0 = bx * 128 + tx * 8;
    #pragma unroll
    for (int i = 0; i < 8; i++) {
        size_t rowoff = (size_t)(m0 + i) * Ndim + n0;
        #pragma unroll
        for (int j4 = 0; j4 < 2; j4++) {
            float4 v;
            v.x = acc[i][j4 * 4 + 0];
            v.y = acc[i][j4 * 4 + 1];
            v.z = acc[i][j4 * 4 + 2];
            v.w = acc[i][j4 * 4 + 3];
            if (BIAS) {
                float4 bb = *(const float4*)(bias + n0 + j4 * 4);
                v.x += bb.x; v.y += bb.y; v.z += bb.z; v.w += bb.w;
            }
            if (RESID) {
                float4 rr = *(const float4*)(Rm + rowoff + j4 * 4);
                v.x += rr.x; v.y += rr.y; v.z += rr.z; v.w += rr.w;
            }
            if (RELU) {
                v.x = fmaxf(v.x, 0.0f); v.y = fmaxf(v.y, 0.0f);
                v.z = fmaxf(v.z, 0.0f); v.w = fmaxf(v.w, 0.0f);
            }
            *(float4*)(C + rowoff + j4 * 4) = v;
        }
    }
}

// ---------------- flash attention: one CTA per (qtile, head, batch) ----------------
#define APAD 68
__global__ __launch_bounds__(256) void attn_kernel(const float* __restrict__ qkv,
                                                   float* __restrict__ out) {
    extern __shared__ float sm[];
    float* Qt  = sm;                 // [64][APAD] transposed: Qt[d][r]
    float* Kst = sm + 64 * APAD;     // Kst[d][kc]
    float* Vs  = sm + 2 * 64 * APAD; // Vs[kc][d]
    float* St  = sm + 3 * 64 * APAD; // St[kc][qr]

    int qt = blockIdx.x, h = blockIdx.y, b = blockIdx.z;
    int tid = threadIdx.x, tx = tid & 15, ty = tid >> 4;
    int t0 = qt * 64;
    size_t base = (size_t)b * T_ * 3072;

    // load Q tile transposed
    #pragma unroll
    for (int l = 0; l < 4; l++) {
        int idx = l * 256 + tid;
        int r = idx >> 4;
        int d4 = (idx & 15) * 4;
        float4 v = *(const float4*)(qkv + base + (size_t)(t0 + r) * 3072 + h * 64 + d4);
        Qt[(d4 + 0) * APAD + r] = v.x;
        Qt[(d4 + 1) * APAD + r] = v.y;
        Qt[(d4 + 2) * APAD + r] = v.z;
        Qt[(d4 + 3) * APAD + r] = v.w;
    }

    float o[4][4];
    float m[4], l_[4];
    #pragma unroll
    for (int i = 0; i < 4; i++) {
        m[i] = -1e30f; l_[i] = 0.0f;
        #pragma unroll
        for (int j = 0; j < 4; j++) o[i][j] = 0.0f;
    }

    for (int ktile = 0; ktile <= qt; ++ktile) {
        __syncthreads();
        int k0 = ktile * 64;
        #pragma unroll
        for (int l = 0; l < 4; l++) {
            int idx = l * 256 + tid;
            int r = idx >> 4;
            int d4 = (idx & 15) * 4;
            float4 kv = *(const float4*)(qkv + base + (size_t)(k0 + r) * 3072 + 1024 + h * 64 + d4);
            Kst[(d4 + 0) * APAD + r] = kv.x;
            Kst[(d4 + 1) * APAD + r] = kv.y;
            Kst[(d4 + 2) * APAD + r] = kv.z;
            Kst[(d4 + 3) * APAD + r] = kv.w;
            float4 vv = *(const float4*)(qkv + base + (size_t)(k0 + r) * 3072 + 2048 + h * 64 + d4);
            *(float4*)&Vs[r * APAD + d4] = vv;
        }
        __syncthreads();

        float s[4][4];
        #pragma unroll
        for (int i = 0; i < 4; i++)
            #pragma unroll
            for (int j = 0; j < 4; j++) s[i][j] = 0.0f;

        for (int d = 0; d < 64; d++) {
            float4 a = *(float4*)&Qt[d * APAD + ty * 4];
            float4 c = *(float4*)&Kst[d * APAD + tx * 4];
            float av[4] = {a.x, a.y, a.z, a.w};
            float cv[4] = {c.x, c.y, c.z, c.w};
            #pragma unroll
            for (int i = 0; i < 4; i++)
                #pragma unroll
                for (int j = 0; j < 4; j++) s[i][j] += av[i] * cv[j];
        }
        #pragma unroll
        for (int i = 0; i < 4; i++)
            #pragma unroll
            for (int j = 0; j < 4; j++) s[i][j] *= SCALE;

        if (ktile == qt) {
            #pragma unroll
            for (int i = 0; i < 4; i++)
                #pragma unroll
                for (int j = 0; j < 4; j++)
                    if (k0 + tx * 4 + j > t0 + ty * 4 + i) s[i][j] = -1e30f;
        }

        #pragma unroll
        for (int i = 0; i < 4; i++) {
            float mx = fmaxf(fmaxf(s[i][0], s[i][1]), fmaxf(s[i][2], s[i][3]));
            #pragma unroll
            for (int off = 8; off > 0; off >>= 1)
                mx = fmaxf(mx, __shfl_xor_sync(0xffffffffu, mx, off, 16));
            float mn = fmaxf(m[i], mx);
            float al = __expf(m[i] - mn);
            float rs = 0.0f;
            #pragma unroll
            for (int j = 0; j < 4; j++) {
                float p = __expf(s[i][j] - mn);
                s[i][j] = p;
                rs += p;
            }
            #pragma unroll
            for (int off = 8; off > 0; off >>= 1)
                rs += __shfl_xor_sync(0xffffffffu, rs, off, 16);
            l_[i] = l_[i] * al + rs;
            m[i] = mn;
            #pragma unroll
            for (int j = 0; j < 4; j++) o[i][j] *= al;
            #pragma unroll
            for (int j = 0; j < 4; j++)
                St[(tx * 4 + j) * APAD + ty * 4 + i] = s[i][j];
        }
        __syncthreads();

        for (int kc = 0; kc < 64; kc++) {
            float4 a = *(float4*)&St[kc * APAD + ty * 4];
            float4 vv = *(float4*)&Vs[kc * APAD + tx * 4];
            float av[4] = {a.x, a.y, a.z, a.w};
            float bv[4] = {vv.x, vv.y, vv.z, vv.w};
            #pragma unroll
            for (int i = 0; i < 4; i++)
                #pragma unroll
                for (int j = 0; j < 4; j++) o[i][j] += av[i] * bv[j];
        }
    }

    #pragma unroll
    for (int i = 0; i < 4; i++) {
        float inv = 1.0f / l_[i];
        float4 v;
        v.x = o[i][0] * inv; v.y = o[i][1] * inv;
        v.z = o[i][2] * inv; v.w = o[i][3] * inv;
        *(float4*)(out + ((size_t)b * T_ + t0 + ty * 4 + i) * E_ + h * 64 + tx * 4) = v;
    }
}

// ---------------- launch ----------------
extern "C" void kernel_launch(void* const* d_in, const int* in_sizes, int n_in,
                              void* d_out, int out_size) {
    const float* x     = (const float*)d_in[0];
    const float* Wq    = (const float*)d_in[1];
    const float* Wk    = (const float*)d_in[2];
    const float* Wv    = (const float*)d_in[3];
    const float* Wo    = (const float*)d_in[4];
    const float* bo    = (const float*)d_in[5];
    const float* W1    = (const float*)d_in[6];
    const float* b1    = (const float*)d_in[7];
    const float* W2    = (const float*)d_in[8];
    const float* b2    = (const float*)d_in[9];
    const float* ln1w  = (const float*)d_in[10];
    const float* ln1b  = (const float*)d_in[11];
    const float* ln2w  = (const float*)d_in[12];
    const float* ln2b  = (const float*)d_in[13];
    float* out = (float*)d_out;

    float *h, *w3, *qkv, *attn, *x2, *u;
    cudaGetSymbolAddress((void**)&h, g_h);
    cudaGetSymbolAddress((void**)&w3, g_w3);
    cudaGetSymbolAddress((void**)&qkv, g_qkv);
    cudaGetSymbolAddress((void**)&attn, g_attn);
    cudaGetSymbolAddress((void**)&x2, g_x2);
    cudaGetSymbolAddress((void**)&u, g_u);

    cudaFuncSetAttribute(attn_kernel, cudaFuncAttributeMaxDynamicSharedMemorySize,
                         4 * 64 * APAD * 4);

    // 1. pack QKV weights into [1024][3072]
    pack_w_kernel<<<(3 * E_ * E_) / 256, 256>>>(Wq, Wk, Wv, w3);

    // 2. LN1
    ln_kernel<<<M_, 256>>>(x, ln1w, ln1b, h);

    // 3. QKV: [20480,1024] @ [1024,3072]
    gemm128_kernel<false, false, false><<<dim3(3072 / 128, M_ / 128), 256>>>(
        h, w3, nullptr, nullptr, qkv, 3072, E_);

    // 4. attention
    attn_kernel<<<dim3(T_ / 64, H_, B_), 256, 4 * 64 * APAD * 4>>>(qkv, attn);

    // 5. out-proj + bias + residual(x)
    gemm128_kernel<true, true, false><<<dim3(E_ / 128, M_ / 128), 256>>>(
        attn, Wo, bo, x, x2, E_, E_);

    // 6. LN2
    ln_kernel<<<M_, 256>>>(x2, ln2w, ln2b, h);

    // 7. FFN1: relu(h @ W1 + b1)
    gemm128_kernel<true, false, true><<<dim3(P_ / 128, M_ / 128), 256>>>(
        h, W1, b1, nullptr, u, P_, E_);

    // 8. FFN2: x2 + u @ W2 + b2 -> out
    gemm128_kernel<true, true, false><<<dim3(E_ / 128, M_ / 128), 256>>>(
        u, W2, b2, x2, out, E_, P_);
}